// round 1
// baseline (speedup 1.0000x reference)
#include <cuda_runtime.h>

namespace {

constexpr int T_STEPS = 512;
constexpr int TILE_B  = 16;
constexpr int THREADS = 256;
constexpr int GRID    = 2048 / TILE_B;   // 128 CTAs

struct SM {
  float4 W1T[64 * 64];    // [k][u] -> gates (i,f,g,o) of Whh0^T
  float4 W2T[128 * 64];   // [k][u] -> gates of [Wih1; Whh1]^T
  float4 hcat[128 * 4];   // rows 0..63 = h1, 64..127 = h2; row = 16 floats (b slots)
  float  Gbuf[16 * 256];  // partial-sum exchange, transposed: [j=16][tid]
  float  xbuf[16 * 64];   // x chunk [b slot][64 timesteps]
  float4 wih0g[64];       // Wih0 gate-interleaved per unit
  float4 bs0[64];         // bih0+bhh0 gate-interleaved
  float4 bs1[64];
  float  fcWs[64];
};

__device__ __forceinline__ float sigf(float v) {
  // 1/(1+e^-v): EX2 + RCP. Saturation safe: exp->inf => rcp->0.
  return __fdividef(1.0f, 1.0f + __expf(-v));
}
__device__ __forceinline__ float tanhfa(float v) {
  // tanh(v) = 2*sigmoid(2v) - 1, saturation safe.
  return 2.0f * __fdividef(1.0f, 1.0f + __expf(-2.0f * v)) - 1.0f;
}

// Exchange k-half partials, apply gates, update c, write h row. 2 syncthreads.
template <bool L1>
__device__ __forceinline__ void gate_phase(
    SM* S, float* hcatf, float (&acc)[4][8], float (&c)[4],
    float4 bias, float4 wx, int tid, int s, int wslot, int bq, int hrow, int xoff)
{
  // scatter the quad our k-partner will act on (partner reads Gbuf[j][its tid])
  if (s == 0) {
#pragma unroll
    for (int g = 0; g < 4; ++g)
#pragma unroll
      for (int b = 0; b < 4; ++b)
        S->Gbuf[(g * 4 + b) * 256 + wslot] = acc[g][4 + b];
  } else {
#pragma unroll
    for (int g = 0; g < 4; ++g)
#pragma unroll
      for (int b = 0; b < 4; ++b)
        S->Gbuf[(g * 4 + b) * 256 + wslot] = acc[g][b];
  }
  __syncthreads();

  float hnew[4];
#pragma unroll
  for (int b = 0; b < 4; ++b) {
    float gg[4];
    if (s == 0) {
#pragma unroll
      for (int g = 0; g < 4; ++g)
        gg[g] = acc[g][b] + S->Gbuf[(g * 4 + b) * 256 + tid];
    } else {
#pragma unroll
      for (int g = 0; g < 4; ++g)
        gg[g] = acc[g][4 + b] + S->Gbuf[(g * 4 + b) * 256 + tid];
    }
    float gi = gg[0] + bias.x;
    float gf = gg[1] + bias.y;
    float gc = gg[2] + bias.z;
    float go = gg[3] + bias.w;
    if (L1) {
      float xv = S->xbuf[(bq + b) * 64 + xoff];
      gi += xv * wx.x;
      gf += xv * wx.y;
      gc += xv * wx.z;
      go += xv * wx.w;
    }
    float iv = sigf(gi);
    float fv = sigf(gf);
    float gv = tanhfa(gc);
    float ov = sigf(go);
    float cn = fv * c[b] + iv * gv;
    c[b] = cn;
    hnew[b] = ov * tanhfa(cn);
  }
  // write our 4 h values (16B aligned: bq is a multiple of 4)
  *reinterpret_cast<float4*>(&hcatf[hrow * 16 + bq]) =
      make_float4(hnew[0], hnew[1], hnew[2], hnew[3]);
  __syncthreads();
}

}  // namespace

__global__ void __launch_bounds__(THREADS, 1) lstm2_kernel(
    const float* __restrict__ x,
    const float* __restrict__ Wih0, const float* __restrict__ Whh0,
    const float* __restrict__ bih0, const float* __restrict__ bhh0,
    const float* __restrict__ Wih1, const float* __restrict__ Whh1,
    const float* __restrict__ bih1, const float* __restrict__ bhh1,
    const float* __restrict__ fcW,  const float* __restrict__ fcb,
    float* __restrict__ out)
{
  extern __shared__ char smraw[];
  SM* S = reinterpret_cast<SM*>(smraw);
  const int tid = threadIdx.x;
  const int u   = tid & 63;          // hidden unit
  const int s   = (tid >> 6) & 1;    // k-half
  const int G   = tid >> 7;          // batch group of 8
  const int bBase = blockIdx.x * TILE_B;

  float* W1Tf  = reinterpret_cast<float*>(S->W1T);
  float* W2Tf  = reinterpret_cast<float*>(S->W2T);
  float* hcatf = reinterpret_cast<float*>(S->hcat);

  // ---- stage weights (transposed, gate-interleaved) ----
  for (int idx = tid; idx < 256 * 64; idx += THREADS) {
    int j = idx >> 6, k = idx & 63;
    W1Tf[(k * 64 + (j & 63)) * 4 + (j >> 6)] = Whh0[idx];
  }
  for (int idx = tid; idx < 256 * 128; idx += THREADS) {
    int j = idx >> 7, k = idx & 127;
    float w = (k < 64) ? Wih1[j * 64 + k] : Whh1[j * 64 + (k - 64)];
    W2Tf[(k * 64 + (j & 63)) * 4 + (j >> 6)] = w;
  }
  {
    int j = tid, g = j >> 6, uu = j & 63;
    reinterpret_cast<float*>(S->wih0g)[uu * 4 + g] = Wih0[j];
    reinterpret_cast<float*>(S->bs0)[uu * 4 + g]   = bih0[j] + bhh0[j];
    reinterpret_cast<float*>(S->bs1)[uu * 4 + g]   = bih1[j] + bhh1[j];
  }
  if (tid < 64) S->fcWs[tid] = fcW[tid];
  for (int idx = tid; idx < 128 * 16; idx += THREADS) hcatf[idx] = 0.0f;
  __syncthreads();

  const float4 wx  = S->wih0g[u];
  const float4 b0r = S->bs0[u];
  const float4 b1r = S->bs1[u];

  float c1[4] = {0.f, 0.f, 0.f, 0.f};
  float c2[4] = {0.f, 0.f, 0.f, 0.f};

  const int wslot = (G << 7) | ((1 - s) << 6) | u;  // partner's tid
  const int bq = G * 8 + s * 4;                     // act b-slot base (local)
  const int hq = G * 2;                             // float4 quad base in hcat row

  for (int t = 0; t < T_STEPS; ++t) {
    if ((t & 63) == 0) {
      // stage 64 timesteps of x for all 16 batches (coalesced float4)
      int bb = tid >> 4, tq = tid & 15;
      float4 v = *reinterpret_cast<const float4*>(
          x + (size_t)(bBase + bb) * T_STEPS + t + tq * 4);
      *reinterpret_cast<float4*>(&S->xbuf[bb * 64 + tq * 4]) = v;
      __syncthreads();
    }

    // ===== layer 1 matvec: g1 = Whh0 * h1_{t-1}, k-half per thread =====
    float acc[4][8];
#pragma unroll
    for (int g = 0; g < 4; ++g)
#pragma unroll
      for (int b = 0; b < 8; ++b) acc[g][b] = 0.0f;

    {
      const int k0 = s * 32;
#pragma unroll 8
      for (int kk = 0; kk < 32; ++kk) {
        int k = k0 + kk;
        float4 w  = S->W1T[k * 64 + u];
        float4 hA = S->hcat[k * 4 + hq];
        float4 hB = S->hcat[k * 4 + hq + 1];
        float ws[4] = {w.x, w.y, w.z, w.w};
        float hs[8] = {hA.x, hA.y, hA.z, hA.w, hB.x, hB.y, hB.z, hB.w};
#pragma unroll
        for (int g = 0; g < 4; ++g)
#pragma unroll
          for (int b = 0; b < 8; ++b) acc[g][b] += ws[g] * hs[b];
      }
    }
    gate_phase<true>(S, hcatf, acc, c1, b0r, wx, tid, s, wslot, bq,
                     /*hrow=*/u, /*xoff=*/t & 63);

    // ===== layer 2 matvec: g2 = [Wih1;Whh1] * [h1_t ; h2_{t-1}] =====
#pragma unroll
    for (int g = 0; g < 4; ++g)
#pragma unroll
      for (int b = 0; b < 8; ++b) acc[g][b] = 0.0f;

    {
      const int k0 = s * 64;
#pragma unroll 8
      for (int kk = 0; kk < 64; ++kk) {
        int k = k0 + kk;
        float4 w  = S->W2T[k * 64 + u];
        float4 hA = S->hcat[k * 4 + hq];
        float4 hB = S->hcat[k * 4 + hq + 1];
        float ws[4] = {w.x, w.y, w.z, w.w};
        float hs[8] = {hA.x, hA.y, hA.z, hA.w, hB.x, hB.y, hB.z, hB.w};
#pragma unroll
        for (int g = 0; g < 4; ++g)
#pragma unroll
          for (int b = 0; b < 8; ++b) acc[g][b] += ws[g] * hs[b];
      }
    }
    gate_phase<false>(S, hcatf, acc, c2, b1r, wx, tid, s, wslot, bq,
                      /*hrow=*/64 + u, /*xoff=*/0);
  }

  // ===== FC epilogue: out[b] = fcW . h2_{T-1} + fcb =====
  if (tid < TILE_B) {
    float accO = fcb[0];
#pragma unroll 8
    for (int uu = 0; uu < 64; ++uu)
      accO += S->fcWs[uu] * hcatf[(64 + uu) * 16 + tid];
    out[bBase + tid] = accO;
  }
}

extern "C" void kernel_launch(void* const* d_in, const int* in_sizes, int n_in,
                              void* d_out, int out_size) {
  (void)in_sizes; (void)n_in; (void)out_size;
  cudaFuncSetAttribute(lstm2_kernel,
                       cudaFuncAttributeMaxDynamicSharedMemorySize,
                       (int)sizeof(SM));
  lstm2_kernel<<<GRID, THREADS, sizeof(SM)>>>(
      (const float*)d_in[0],
      (const float*)d_in[1], (const float*)d_in[2],
      (const float*)d_in[3], (const float*)d_in[4],
      (const float*)d_in[5], (const float*)d_in[6],
      (const float*)d_in[7], (const float*)d_in[8],
      (const float*)d_in[9], (const float*)d_in[10],
      (float*)d_out);
}